// round 9
// baseline (speedup 1.0000x reference)
#include <cuda_runtime.h>
#include <math.h>

// ---------------------------------------------------------------------------
// GAT_23888608101379: 3-layer GAT + mean pool + linear head, fp32.
//   - edge_index dtype detected on-device (int32 vs int64) -> g_src/g_dst
//   - CSR-by-dst built once per launch (histogram + scan + scatter)
//   - per layer: tiled fp32 GEMM -> alpha dots (warp/node)
//                -> softmax (warp/dst over CSR) -> aggregation (block/dst)
//   - final: column mean over nodes + 64x64 head
// ---------------------------------------------------------------------------

constexpr int CN = 50000;            // nodes
constexpr int CE = 800000;           // edges
constexpr int CT = CE + CN;          // edges + self loops

// scratch (device globals: allocation-free)
__device__ float g_bufA[(size_t)CN * 256];
__device__ float g_bufB[(size_t)CN * 256];
__device__ float g_h2  [(size_t)CN * 64];
__device__ float g_out2[(size_t)CN * 64];
__device__ float g_as  [CN * 4];
__device__ float g_ad  [CN * 4];
__device__ float g_w   [(size_t)CT * 4];
__device__ int   g_src [CE];
__device__ int   g_dst [CE];
__device__ int   g_rowptr[CN + 1];
__device__ int   g_counts[CN];
__device__ int   g_cursor[CN];
__device__ int   g_adj   [CT];
__device__ float g_gsum[64];
__device__ int   g_is64;

// ----------------------- edge dtype detect + convert ------------------------
// If int64 (LE) with values < 2^31, all odd 32-bit words are 0.
// If int32, odd words are random edge indices -> some nonzero.

__global__ void k_detect(const int* __restrict__ w) {
    __shared__ int any;
    if (threadIdx.x == 0) any = 0;
    __syncthreads();
    for (int i = threadIdx.x; i < 4096; i += blockDim.x)
        if (w[2 * i + 1] != 0) any = 1;
    __syncthreads();
    if (threadIdx.x == 0) g_is64 = (any == 0) ? 1 : 0;
}

__global__ void k_convert(const void* __restrict__ ei, int e) {
    int i = blockIdx.x * blockDim.x + threadIdx.x;
    if (i >= e) return;
    int s, d;
    if (g_is64) {
        const long long* p = (const long long*)ei;
        s = (int)p[i];
        d = (int)p[(size_t)e + i];
    } else {
        const int* p = (const int*)ei;
        s = p[i];
        d = p[(size_t)e + i];
    }
    g_src[i] = s;
    g_dst[i] = d;
}

// ---------------------------- CSR build -------------------------------------

__global__ void k_init(int n) {
    int i = blockIdx.x * blockDim.x + threadIdx.x;
    if (i < n)  g_counts[i] = 1;      // self loop contributes 1 per node
    if (i < 64) g_gsum[i] = 0.f;
}

__global__ void k_hist(int e, int n) {
    int i = blockIdx.x * blockDim.x + threadIdx.x;
    if (i < e) {
        int d = g_dst[i];
        if (d >= 0 && d < n) atomicAdd(&g_counts[d], 1);
    }
}

// single-block chunked exclusive scan of counts -> rowptr (+cursor copy)
__global__ void k_scan(int n) {
    __shared__ int sh[1024];
    __shared__ int carry;
    if (threadIdx.x == 0) carry = 0;
    __syncthreads();
    for (int base = 0; base < n; base += 1024) {
        int i = base + threadIdx.x;
        int v = (i < n) ? g_counts[i] : 0;
        sh[threadIdx.x] = v;
        __syncthreads();
        int c = carry;
        #pragma unroll
        for (int off = 1; off < 1024; off <<= 1) {
            int t = (threadIdx.x >= off) ? sh[threadIdx.x - off] : 0;
            __syncthreads();
            sh[threadIdx.x] += t;
            __syncthreads();
        }
        int excl = sh[threadIdx.x] - v;
        if (i < n) { g_rowptr[i] = c + excl; g_cursor[i] = c + excl; }
        __syncthreads();
        if (threadIdx.x == 0) carry = c + sh[1023];
        __syncthreads();
    }
    if (threadIdx.x == 0) g_rowptr[n] = carry;
}

__global__ void k_scatter(int e, int n) {
    int i = blockIdx.x * blockDim.x + threadIdx.x;
    if (i < e) {
        int s = g_src[i];
        int d = g_dst[i];
        if (d >= 0 && d < n && s >= 0 && s < n) {
            int pos = atomicAdd(&g_cursor[d], 1);
            g_adj[pos] = s;
        }
    } else if (i < e + n) {
        int nd = i - e;                       // self loop
        int pos = atomicAdd(&g_cursor[nd], 1);
        g_adj[pos] = nd;
    }
}

// ------------------------------ GEMM ----------------------------------------
// C[M,N] = A[M,K] @ B[K,N], fp32, BM=128, BK=16, BN in {128,64}, 256 threads.

template <int BN, int TN>
__global__ __launch_bounds__(256) void k_gemm(const float* __restrict__ A,
                                              const float* __restrict__ B,
                                              float* __restrict__ C,
                                              int M, int N, int K) {
    __shared__ float As[16][128];
    __shared__ float Bs[16][BN];
    const int rowBase = blockIdx.x * 128;
    const int colBase = blockIdx.y * BN;
    const int tid = threadIdx.x;
    const int tx = tid & 15;
    const int ty = tid >> 4;

    float acc[8][TN];
    #pragma unroll
    for (int i = 0; i < 8; i++)
        #pragma unroll
        for (int j = 0; j < TN; j++) acc[i][j] = 0.f;

    for (int k0 = 0; k0 < K; k0 += 16) {
        // A tile 128x16 -> transposed into As[k][m]
        #pragma unroll
        for (int it = 0; it < 2; ++it) {
            int ld = tid + it * 256;
            int r = ld >> 2;
            int c4 = (ld & 3) << 2;
            float4 v = make_float4(0.f, 0.f, 0.f, 0.f);
            int gr = rowBase + r;
            if (gr < M)
                v = *reinterpret_cast<const float4*>(A + (size_t)gr * K + k0 + c4);
            As[c4 + 0][r] = v.x; As[c4 + 1][r] = v.y;
            As[c4 + 2][r] = v.z; As[c4 + 3][r] = v.w;
        }
        // B tile 16xBN
        #pragma unroll
        for (int it = 0; it < (16 * BN) / 1024; ++it) {
            int ld = tid + it * 256;
            int kk = ld / (BN / 4);
            int cc = (ld % (BN / 4)) * 4;
            *reinterpret_cast<float4*>(&Bs[kk][cc]) =
                *reinterpret_cast<const float4*>(B + (size_t)(k0 + kk) * N + colBase + cc);
        }
        __syncthreads();
        #pragma unroll
        for (int kk = 0; kk < 16; ++kk) {
            float a[8], b[TN];
            #pragma unroll
            for (int i = 0; i < 8; i++) a[i] = As[kk][ty * 8 + i];
            #pragma unroll
            for (int j = 0; j < TN; j++) b[j] = Bs[kk][tx * TN + j];
            #pragma unroll
            for (int i = 0; i < 8; i++)
                #pragma unroll
                for (int j = 0; j < TN; j++)
                    acc[i][j] = fmaf(a[i], b[j], acc[i][j]);
        }
        __syncthreads();
    }
    #pragma unroll
    for (int i = 0; i < 8; i++) {
        int gr = rowBase + ty * 8 + i;
        if (gr < M) {
            #pragma unroll
            for (int j = 0; j < TN; j += 4) {
                float4 v = make_float4(acc[i][j], acc[i][j + 1], acc[i][j + 2], acc[i][j + 3]);
                *reinterpret_cast<float4*>(C + (size_t)gr * N + colBase + tx * TN + j) = v;
            }
        }
    }
}

// ----------------------- attention scalar dots ------------------------------
// warp per node: alpha_s[n,h] = <h[n,h,:], a_s[h,:]>, likewise alpha_d.

template <int H>
__global__ void k_alpha(const float* __restrict__ h, const float* __restrict__ av_s,
                        const float* __restrict__ av_d, int n) {
    int gw = (blockIdx.x * blockDim.x + threadIdx.x) >> 5;
    int lane = threadIdx.x & 31;
    if (gw >= n) return;
    const int HC = H * 64;
    float ps[H], pd[H];
    #pragma unroll
    for (int hh = 0; hh < H; ++hh) { ps[hh] = 0.f; pd[hh] = 0.f; }
    #pragma unroll
    for (int i = 0; i < HC / 32; ++i) {
        int idx = lane + i * 32;                 // head = i>>1 (compile-time)
        float hv = h[(size_t)gw * HC + idx];
        ps[i >> 1] += hv * av_s[idx];
        pd[i >> 1] += hv * av_d[idx];
    }
    #pragma unroll
    for (int hh = 0; hh < H; ++hh) {
        #pragma unroll
        for (int off = 16; off > 0; off >>= 1) {
            ps[hh] += __shfl_xor_sync(0xffffffffu, ps[hh], off);
            pd[hh] += __shfl_xor_sync(0xffffffffu, pd[hh], off);
        }
    }
    if (lane == 0) {
        #pragma unroll
        for (int hh = 0; hh < H; ++hh) {
            g_as[gw * H + hh] = ps[hh];
            g_ad[gw * H + hh] = pd[hh];
        }
    }
}

// ------------------------- per-dst softmax -----------------------------------
// warp per dst: e = lrelu(as[src]+ad[dst]); normalized weights into g_w

template <int H>
__global__ void k_att(int n) {
    int gw = (blockIdx.x * blockDim.x + threadIdx.x) >> 5;
    int lane = threadIdx.x & 31;
    if (gw >= n) return;
    int r0 = g_rowptr[gw], r1 = g_rowptr[gw + 1];
    float ad[H], mx[H];
    #pragma unroll
    for (int hh = 0; hh < H; ++hh) { ad[hh] = g_ad[gw * H + hh]; mx[hh] = -1e30f; }
    for (int p = r0 + lane; p < r1; p += 32) {
        int s = g_adj[p];
        #pragma unroll
        for (int hh = 0; hh < H; ++hh) {
            float e = g_as[s * H + hh] + ad[hh];
            e = (e > 0.f) ? e : 0.2f * e;        // leaky_relu 0.2
            g_w[(size_t)p * H + hh] = e;
            mx[hh] = fmaxf(mx[hh], e);
        }
    }
    #pragma unroll
    for (int hh = 0; hh < H; ++hh)
        #pragma unroll
        for (int off = 16; off > 0; off >>= 1)
            mx[hh] = fmaxf(mx[hh], __shfl_xor_sync(0xffffffffu, mx[hh], off));
    float sm[H];
    #pragma unroll
    for (int hh = 0; hh < H; ++hh) sm[hh] = 0.f;
    for (int p = r0 + lane; p < r1; p += 32) {
        #pragma unroll
        for (int hh = 0; hh < H; ++hh) {
            float ex = expf(g_w[(size_t)p * H + hh] - mx[hh]);
            g_w[(size_t)p * H + hh] = ex;
            sm[hh] += ex;
        }
    }
    #pragma unroll
    for (int hh = 0; hh < H; ++hh)
        #pragma unroll
        for (int off = 16; off > 0; off >>= 1)
            sm[hh] += __shfl_xor_sync(0xffffffffu, sm[hh], off);
    float inv[H];
    #pragma unroll
    for (int hh = 0; hh < H; ++hh) inv[hh] = 1.f / (sm[hh] + 1e-16f);
    for (int p = r0 + lane; p < r1; p += 32) {
        #pragma unroll
        for (int hh = 0; hh < H; ++hh)
            g_w[(size_t)p * H + hh] *= inv[hh];
    }
}

// --------------------------- aggregation -------------------------------------
// block per dst (blockDim = H*64): out[dst,:] = bias + sum_e w_e * h[src_e,:]

template <int H, bool RELU>
__global__ void k_agg(const float* __restrict__ hin, const float* __restrict__ bias,
                      float* __restrict__ out, int n) {
    int dst = blockIdx.x;
    if (dst >= n) return;
    const int HC = H * 64;
    int tid = threadIdx.x;
    int head = tid >> 6;
    float acc = bias[tid];
    int p = g_rowptr[dst], pe = g_rowptr[dst + 1];
    // 2-way unroll for MLP
    for (; p + 1 < pe; p += 2) {
        int sA = g_adj[p], sB = g_adj[p + 1];
        float wA = g_w[(size_t)p * H + head];
        float wB = g_w[(size_t)(p + 1) * H + head];
        float hA = hin[(size_t)sA * HC + tid];
        float hB = hin[(size_t)sB * HC + tid];
        acc = fmaf(wA, hA, acc);
        acc = fmaf(wB, hB, acc);
    }
    if (p < pe) {
        int s = g_adj[p];
        acc = fmaf(g_w[(size_t)p * H + head], hin[(size_t)s * HC + tid], acc);
    }
    if (RELU) acc = fmaxf(acc, 0.f);
    out[(size_t)dst * HC + tid] = acc;
}

// ------------------------- mean pool + head -----------------------------------

__global__ void k_reduce(const float* __restrict__ h2, int n) {
    __shared__ float sh[256];
    int c = threadIdx.x & 63;
    int rl = threadIdx.x >> 6;
    int rbase = blockIdx.x * 256;
    int rend = min(n, rbase + 256);
    float acc = 0.f;
    for (int r = rbase + rl; r < rend; r += 4)
        acc += h2[(size_t)r * 64 + c];
    sh[threadIdx.x] = acc;
    __syncthreads();
    if (threadIdx.x < 64) {
        float v = sh[threadIdx.x] + sh[threadIdx.x + 64] +
                  sh[threadIdx.x + 128] + sh[threadIdx.x + 192];
        atomicAdd(&g_gsum[threadIdx.x], v);
    }
}

__global__ void k_head(const float* __restrict__ hw, const float* __restrict__ hb,
                       float* __restrict__ out, float invN) {
    int o = threadIdx.x;   // 64 threads
    float acc = hb[o];
    #pragma unroll 8
    for (int c = 0; c < 64; ++c)
        acc = fmaf(g_gsum[c] * invN, hw[c * 64 + o], acc);
    out[o] = acc;
}

// ------------------------------ launch ----------------------------------------

extern "C" void kernel_launch(void* const* d_in, const int* in_sizes, int n_in,
                              void* d_out, int out_size) {
    const float* x   = (const float*)d_in[0];
    const void*  ei  = d_in[1];                 // int32 or int64, detected on-device
    const float* W0  = (const float*)d_in[2];
    const float* a0s = (const float*)d_in[3];
    const float* a0d = (const float*)d_in[4];
    const float* b0  = (const float*)d_in[5];
    const float* W1  = (const float*)d_in[6];
    const float* a1s = (const float*)d_in[7];
    const float* a1d = (const float*)d_in[8];
    const float* b1  = (const float*)d_in[9];
    const float* W2  = (const float*)d_in[10];
    const float* a2s = (const float*)d_in[11];
    const float* a2d = (const float*)d_in[12];
    const float* b2  = (const float*)d_in[13];
    const float* hw  = (const float*)d_in[14];
    const float* hb  = (const float*)d_in[15];
    float* out = (float*)d_out;

    int n = in_sizes[0] / 128;   // 50000
    int e = in_sizes[1] / 2;     // 800000

    float *bufA, *bufB, *h2p, *out2p;
    cudaGetSymbolAddress((void**)&bufA,  g_bufA);
    cudaGetSymbolAddress((void**)&bufB,  g_bufB);
    cudaGetSymbolAddress((void**)&h2p,   g_h2);
    cudaGetSymbolAddress((void**)&out2p, g_out2);

    int wblocks = (n + 7) / 8;                 // 8 warps/block node-parallel

    // dtype detect + convert, then CSR build (by dst, with implicit self loops)
    k_detect <<<1, 256>>>((const int*)ei);
    k_convert<<<(e + 255) / 256, 256>>>(ei, e);
    k_init   <<<(n + 255) / 256, 256>>>(n);
    k_hist   <<<(e + 255) / 256, 256>>>(e, n);
    k_scan   <<<1, 1024>>>(n);
    k_scatter<<<(e + n + 255) / 256, 256>>>(e, n);

    dim3 g01((n + 127) / 128, 2);              // N=256
    dim3 g2 ((n + 127) / 128, 1);              // N=64

    // ---- layer 0: x[N,128] @ W0 -> bufA; softmax/agg -> bufB (relu) ----
    k_gemm<128, 8><<<g01, 256>>>(x, W0, bufA, n, 256, 128);
    k_alpha<4><<<wblocks, 256>>>(bufA, a0s, a0d, n);
    k_att<4><<<wblocks, 256>>>(n);
    k_agg<4, true><<<n, 256>>>(bufA, b0, bufB, n);

    // ---- layer 1: bufB @ W1 -> bufA; -> bufB (relu) ----
    k_gemm<128, 8><<<g01, 256>>>(bufB, W1, bufA, n, 256, 256);
    k_alpha<4><<<wblocks, 256>>>(bufA, a1s, a1d, n);
    k_att<4><<<wblocks, 256>>>(n);
    k_agg<4, true><<<n, 256>>>(bufA, b1, bufB, n);

    // ---- layer 2: bufB @ W2 -> h2; -> out2 (no relu) ----
    k_gemm<64, 4><<<g2, 256>>>(bufB, W2, h2p, n, 64, 256);
    k_alpha<1><<<wblocks, 256>>>(h2p, a2s, a2d, n);
    k_att<1><<<wblocks, 256>>>(n);
    k_agg<1, false><<<n, 64>>>(h2p, b2, out2p, n);

    // ---- mean over nodes + linear head ----
    k_reduce<<<(n + 255) / 256, 256>>>(out2p, n);
    k_head<<<1, 64>>>(hw, hb, out, 1.0f / (float)n);
}

// round 10
// speedup vs baseline: 1.1792x; 1.1792x over previous
#include <cuda_runtime.h>
#include <math.h>
#include <stdint.h>

// ---------------------------------------------------------------------------
// GAT_23888608101379: 3-layer GAT + mean pool + linear head.
//   R9: GEMMs moved to tf32 tensor cores (mma.sync.m16n8k8, RNA-rounded
//       inputs, fp32 accumulate). Rest identical to the passing R8 kernel.
// ---------------------------------------------------------------------------

constexpr int CN = 50000;            // nodes
constexpr int CE = 800000;           // edges
constexpr int CT = CE + CN;          // edges + self loops

// scratch (device globals: allocation-free)
__device__ float g_bufA[(size_t)CN * 256];
__device__ float g_bufB[(size_t)CN * 256];
__device__ float g_h2  [(size_t)CN * 64];
__device__ float g_out2[(size_t)CN * 64];
__device__ float g_as  [CN * 4];
__device__ float g_ad  [CN * 4];
__device__ float g_w   [(size_t)CT * 4];
__device__ int   g_src [CE];
__device__ int   g_dst [CE];
__device__ int   g_rowptr[CN + 1];
__device__ int   g_counts[CN];
__device__ int   g_cursor[CN];
__device__ int   g_adj   [CT];
__device__ float g_gsum[64];
__device__ int   g_is64;

// ----------------------- edge dtype detect + convert ------------------------

__global__ void k_detect(const int* __restrict__ w) {
    __shared__ int any;
    if (threadIdx.x == 0) any = 0;
    __syncthreads();
    for (int i = threadIdx.x; i < 4096; i += blockDim.x)
        if (w[2 * i + 1] != 0) any = 1;
    __syncthreads();
    if (threadIdx.x == 0) g_is64 = (any == 0) ? 1 : 0;
}

__global__ void k_convert(const void* __restrict__ ei, int e) {
    int i = blockIdx.x * blockDim.x + threadIdx.x;
    if (i >= e) return;
    int s, d;
    if (g_is64) {
        const long long* p = (const long long*)ei;
        s = (int)p[i];
        d = (int)p[(size_t)e + i];
    } else {
        const int* p = (const int*)ei;
        s = p[i];
        d = p[(size_t)e + i];
    }
    g_src[i] = s;
    g_dst[i] = d;
}

// ---------------------------- CSR build -------------------------------------

__global__ void k_init(int n) {
    int i = blockIdx.x * blockDim.x + threadIdx.x;
    if (i < n)  g_counts[i] = 1;      // self loop contributes 1 per node
    if (i < 64) g_gsum[i] = 0.f;
}

__global__ void k_hist(int e, int n) {
    int i = blockIdx.x * blockDim.x + threadIdx.x;
    if (i < e) {
        int d = g_dst[i];
        if (d >= 0 && d < n) atomicAdd(&g_counts[d], 1);
    }
}

__global__ void k_scan(int n) {
    __shared__ int sh[1024];
    __shared__ int carry;
    if (threadIdx.x == 0) carry = 0;
    __syncthreads();
    for (int base = 0; base < n; base += 1024) {
        int i = base + threadIdx.x;
        int v = (i < n) ? g_counts[i] : 0;
        sh[threadIdx.x] = v;
        __syncthreads();
        int c = carry;
        #pragma unroll
        for (int off = 1; off < 1024; off <<= 1) {
            int t = (threadIdx.x >= off) ? sh[threadIdx.x - off] : 0;
            __syncthreads();
            sh[threadIdx.x] += t;
            __syncthreads();
        }
        int excl = sh[threadIdx.x] - v;
        if (i < n) { g_rowptr[i] = c + excl; g_cursor[i] = c + excl; }
        __syncthreads();
        if (threadIdx.x == 0) carry = c + sh[1023];
        __syncthreads();
    }
    if (threadIdx.x == 0) g_rowptr[n] = carry;
}

__global__ void k_scatter(int e, int n) {
    int i = blockIdx.x * blockDim.x + threadIdx.x;
    if (i < e) {
        int s = g_src[i];
        int d = g_dst[i];
        if (d >= 0 && d < n && s >= 0 && s < n) {
            int pos = atomicAdd(&g_cursor[d], 1);
            g_adj[pos] = s;
        }
    } else if (i < e + n) {
        int nd = i - e;                       // self loop
        int pos = atomicAdd(&g_cursor[nd], 1);
        g_adj[pos] = nd;
    }
}

// --------------------------- tf32 tensor-core GEMM --------------------------
// C[M,N] = A[M,K] @ B[K,N]; BM=128, BK=32, BN in {128,64}; 256 threads.
// Inputs RNA-rounded to tf32 at smem fill; fp32 accumulate.
// smem XOR swizzle: column c of row r stored at c ^ ((r&7)<<2)  -> the
// mma fragment access pattern (8 rows x 4 k-cols per warp) hits 32 banks.

__device__ __forceinline__ uint32_t f2tf32(float f) {
    uint32_t u;
    asm("cvt.rna.tf32.f32 %0, %1;" : "=r"(u) : "f"(f));
    return u;
}

__device__ __forceinline__ void mma_tf32(float* c,
                                         const uint32_t* a, const uint32_t* b) {
    asm volatile(
        "mma.sync.aligned.m16n8k8.row.col.f32.tf32.tf32.f32 "
        "{%0,%1,%2,%3}, {%4,%5,%6,%7}, {%8,%9}, {%0,%1,%2,%3};\n"
        : "+f"(c[0]), "+f"(c[1]), "+f"(c[2]), "+f"(c[3])
        : "r"(a[0]), "r"(a[1]), "r"(a[2]), "r"(a[3]), "r"(b[0]), "r"(b[1]));
}

template <int BN, int WM, int WN>
__global__ __launch_bounds__(256) void k_gemm_tc(const float* __restrict__ A,
                                                 const float* __restrict__ B,
                                                 float* __restrict__ C,
                                                 int M, int N, int K) {
    constexpr int WARPS_M = 128 / WM;            // warp grid
    constexpr int MT = WM / 16;                  // mma tiles per warp (M)
    constexpr int NT = WN / 8;                   // mma tiles per warp (N)

    __shared__ uint32_t As[128][32];             // tf32 bits, swizzled
    __shared__ uint32_t Bs[BN][32];              // [n][k], swizzled

    const int tid  = threadIdx.x;
    const int wid  = tid >> 5;
    const int lane = tid & 31;
    const int g    = lane >> 2;                  // group id (row within tile)
    const int tg   = lane & 3;                   // thread in group (k col)
    const int sw   = g << 2;                     // per-thread bank swizzle

    const int wm = wid % WARPS_M;                // warp row
    const int wn = wid / WARPS_M;                // warp col
    const int rowBase = blockIdx.x * 128;
    const int colBase = blockIdx.y * BN;

    float acc[MT][NT][4];
    #pragma unroll
    for (int mi = 0; mi < MT; mi++)
        #pragma unroll
        for (int ni = 0; ni < NT; ni++)
            #pragma unroll
            for (int q = 0; q < 4; q++) acc[mi][ni][q] = 0.f;

    for (int k0 = 0; k0 < K; k0 += 32) {
        // ---- fill As: 128x32 floats (1024 float4), 4 per thread ----
        #pragma unroll
        for (int it = 0; it < 4; ++it) {
            int idx = tid + it * 256;
            int r  = idx >> 3;
            int c4 = (idx & 7) << 2;
            float4 v = make_float4(0.f, 0.f, 0.f, 0.f);
            int gr = rowBase + r;
            if (gr < M)
                v = *reinterpret_cast<const float4*>(A + (size_t)gr * K + k0 + c4);
            uint32_t t0 = f2tf32(v.x), t1 = f2tf32(v.y),
                     t2 = f2tf32(v.z), t3 = f2tf32(v.w);
            int cs = c4 ^ ((r & 7) << 2);
            uint4* dst = reinterpret_cast<uint4*>(&As[r][cs]);
            *dst = make_uint4(t0, t1, t2, t3);
        }
        // ---- fill Bs (transposed): 32 x BN floats ----
        #pragma unroll
        for (int it = 0; it < (32 * BN) / 1024; ++it) {
            int idx = tid + it * 256;
            int n4 = (idx % (BN / 4)) * 4;
            int k  = idx / (BN / 4);
            float4 v = *reinterpret_cast<const float4*>(
                B + (size_t)(k0 + k) * N + colBase + n4);
            Bs[n4 + 0][k ^ (((n4 + 0) & 7) << 2)] = f2tf32(v.x);
            Bs[n4 + 1][k ^ (((n4 + 1) & 7) << 2)] = f2tf32(v.y);
            Bs[n4 + 2][k ^ (((n4 + 2) & 7) << 2)] = f2tf32(v.z);
            Bs[n4 + 3][k ^ (((n4 + 3) & 7) << 2)] = f2tf32(v.w);
        }
        __syncthreads();

        #pragma unroll
        for (int kk = 0; kk < 32; kk += 8) {
            uint32_t af[MT][4], bf[NT][2];
            int c0 = (kk + tg) ^ sw;
            int c1 = (kk + tg + 4) ^ sw;
            #pragma unroll
            for (int mi = 0; mi < MT; mi++) {
                int r0 = wm * WM + mi * 16 + g;
                af[mi][0] = As[r0][c0];
                af[mi][1] = As[r0 + 8][c0];
                af[mi][2] = As[r0][c1];
                af[mi][3] = As[r0 + 8][c1];
            }
            #pragma unroll
            for (int ni = 0; ni < NT; ni++) {
                int nn = wn * WN + ni * 8 + g;
                bf[ni][0] = Bs[nn][c0];
                bf[ni][1] = Bs[nn][c1];
            }
            #pragma unroll
            for (int mi = 0; mi < MT; mi++)
                #pragma unroll
                for (int ni = 0; ni < NT; ni++)
                    mma_tf32(acc[mi][ni], af[mi], bf[ni]);
        }
        __syncthreads();
    }

    // ---- epilogue ----
    #pragma unroll
    for (int mi = 0; mi < MT; mi++) {
        int r = rowBase + wm * WM + mi * 16 + g;
        #pragma unroll
        for (int ni = 0; ni < NT; ni++) {
            int c = colBase + wn * WN + ni * 8 + tg * 2;
            if (r < M)
                *reinterpret_cast<float2*>(C + (size_t)r * N + c) =
                    make_float2(acc[mi][ni][0], acc[mi][ni][1]);
            if (r + 8 < M)
                *reinterpret_cast<float2*>(C + (size_t)(r + 8) * N + c) =
                    make_float2(acc[mi][ni][2], acc[mi][ni][3]);
        }
    }
}

// ----------------------- attention scalar dots ------------------------------

template <int H>
__global__ void k_alpha(const float* __restrict__ h, const float* __restrict__ av_s,
                        const float* __restrict__ av_d, int n) {
    int gw = (blockIdx.x * blockDim.x + threadIdx.x) >> 5;
    int lane = threadIdx.x & 31;
    if (gw >= n) return;
    const int HC = H * 64;
    float ps[H], pd[H];
    #pragma unroll
    for (int hh = 0; hh < H; ++hh) { ps[hh] = 0.f; pd[hh] = 0.f; }
    #pragma unroll
    for (int i = 0; i < HC / 32; ++i) {
        int idx = lane + i * 32;
        float hv = h[(size_t)gw * HC + idx];
        ps[i >> 1] += hv * av_s[idx];
        pd[i >> 1] += hv * av_d[idx];
    }
    #pragma unroll
    for (int hh = 0; hh < H; ++hh) {
        #pragma unroll
        for (int off = 16; off > 0; off >>= 1) {
            ps[hh] += __shfl_xor_sync(0xffffffffu, ps[hh], off);
            pd[hh] += __shfl_xor_sync(0xffffffffu, pd[hh], off);
        }
    }
    if (lane == 0) {
        #pragma unroll
        for (int hh = 0; hh < H; ++hh) {
            g_as[gw * H + hh] = ps[hh];
            g_ad[gw * H + hh] = pd[hh];
        }
    }
}

// ------------------------- per-dst softmax -----------------------------------

template <int H>
__global__ void k_att(int n) {
    int gw = (blockIdx.x * blockDim.x + threadIdx.x) >> 5;
    int lane = threadIdx.x & 31;
    if (gw >= n) return;
    int r0 = g_rowptr[gw], r1 = g_rowptr[gw + 1];
    float ad[H], mx[H];
    #pragma unroll
    for (int hh = 0; hh < H; ++hh) { ad[hh] = g_ad[gw * H + hh]; mx[hh] = -1e30f; }
    for (int p = r0 + lane; p < r1; p += 32) {
        int s = g_adj[p];
        #pragma unroll
        for (int hh = 0; hh < H; ++hh) {
            float e = g_as[s * H + hh] + ad[hh];
            e = (e > 0.f) ? e : 0.2f * e;        // leaky_relu 0.2
            g_w[(size_t)p * H + hh] = e;
            mx[hh] = fmaxf(mx[hh], e);
        }
    }
    #pragma unroll
    for (int hh = 0; hh < H; ++hh)
        #pragma unroll
        for (int off = 16; off > 0; off >>= 1)
            mx[hh] = fmaxf(mx[hh], __shfl_xor_sync(0xffffffffu, mx[hh], off));
    float sm[H];
    #pragma unroll
    for (int hh = 0; hh < H; ++hh) sm[hh] = 0.f;
    for (int p = r0 + lane; p < r1; p += 32) {
        #pragma unroll
        for (int hh = 0; hh < H; ++hh) {
            float ex = expf(g_w[(size_t)p * H + hh] - mx[hh]);
            g_w[(size_t)p * H + hh] = ex;
            sm[hh] += ex;
        }
    }
    #pragma unroll
    for (int hh = 0; hh < H; ++hh)
        #pragma unroll
        for (int off = 16; off > 0; off >>= 1)
            sm[hh] += __shfl_xor_sync(0xffffffffu, sm[hh], off);
    float inv[H];
    #pragma unroll
    for (int hh = 0; hh < H; ++hh) inv[hh] = 1.f / (sm[hh] + 1e-16f);
    for (int p = r0 + lane; p < r1; p += 32) {
        #pragma unroll
        for (int hh = 0; hh < H; ++hh)
            g_w[(size_t)p * H + hh] *= inv[hh];
    }
}

// --------------------------- aggregation -------------------------------------

template <int H, bool RELU>
__global__ void k_agg(const float* __restrict__ hin, const float* __restrict__ bias,
                      float* __restrict__ out, int n) {
    int dst = blockIdx.x;
    if (dst >= n) return;
    const int HC = H * 64;
    int tid = threadIdx.x;
    int head = tid >> 6;
    float acc = bias[tid];
    int p = g_rowptr[dst], pe = g_rowptr[dst + 1];
    for (; p + 1 < pe; p += 2) {
        int sA = g_adj[p], sB = g_adj[p + 1];
        float wA = g_w[(size_t)p * H + head];
        float wB = g_w[(size_t)(p + 1) * H + head];
        float hA = hin[(size_t)sA * HC + tid];
        float hB = hin[(size_t)sB * HC + tid];
        acc = fmaf(wA, hA, acc);
        acc = fmaf(wB, hB, acc);
    }
    if (p < pe) {
        int s = g_adj[p];
        acc = fmaf(g_w[(size_t)p * H + head], hin[(size_t)s * HC + tid], acc);
    }
    if (RELU) acc = fmaxf(acc, 0.f);
    out[(size_t)dst * HC + tid] = acc;
}

// ------------------------- mean pool + head -----------------------------------

__global__ void k_reduce(const float* __restrict__ h2, int n) {
    __shared__ float sh[256];
    int c = threadIdx.x & 63;
    int rl = threadIdx.x >> 6;
    int rbase = blockIdx.x * 256;
    int rend = min(n, rbase + 256);
    float acc = 0.f;
    for (int r = rbase + rl; r < rend; r += 4)
        acc += h2[(size_t)r * 64 + c];
    sh[threadIdx.x] = acc;
    __syncthreads();
    if (threadIdx.x < 64) {
        float v = sh[threadIdx.x] + sh[threadIdx.x + 64] +
                  sh[threadIdx.x + 128] + sh[threadIdx.x + 192];
        atomicAdd(&g_gsum[threadIdx.x], v);
    }
}

__global__ void k_head(const float* __restrict__ hw, const float* __restrict__ hb,
                       float* __restrict__ out, float invN) {
    int o = threadIdx.x;   // 64 threads
    float acc = hb[o];
    #pragma unroll 8
    for (int c = 0; c < 64; ++c)
        acc = fmaf(g_gsum[c] * invN, hw[c * 64 + o], acc);
    out[o] = acc;
}

// ------------------------------ launch ----------------------------------------

extern "C" void kernel_launch(void* const* d_in, const int* in_sizes, int n_in,
                              void* d_out, int out_size) {
    const float* x   = (const float*)d_in[0];
    const void*  ei  = d_in[1];                 // int32 or int64, detected on-device
    const float* W0  = (const float*)d_in[2];
    const float* a0s = (const float*)d_in[3];
    const float* a0d = (const float*)d_in[4];
    const float* b0  = (const float*)d_in[5];
    const float* W1  = (const float*)d_in[6];
    const float* a1s = (const float*)d_in[7];
    const float* a1d = (const float*)d_in[8];
    const float* b1  = (const float*)d_in[9];
    const float* W2  = (const float*)d_in[10];
    const float* a2s = (const float*)d_in[11];
    const float* a2d = (const float*)d_in[12];
    const float* b2  = (const float*)d_in[13];
    const float* hw  = (const float*)d_in[14];
    const float* hb  = (const float*)d_in[15];
    float* out = (float*)d_out;

    int n = in_sizes[0] / 128;   // 50000
    int e = in_sizes[1] / 2;     // 800000

    float *bufA, *bufB, *h2p, *out2p;
    cudaGetSymbolAddress((void**)&bufA,  g_bufA);
    cudaGetSymbolAddress((void**)&bufB,  g_bufB);
    cudaGetSymbolAddress((void**)&h2p,   g_h2);
    cudaGetSymbolAddress((void**)&out2p, g_out2);

    int wblocks = (n + 7) / 8;                 // 8 warps/block node-parallel

    // dtype detect + convert, then CSR build (by dst, with implicit self loops)
    k_detect <<<1, 256>>>((const int*)ei);
    k_convert<<<(e + 255) / 256, 256>>>(ei, e);
    k_init   <<<(n + 255) / 256, 256>>>(n);
    k_hist   <<<(e + 255) / 256, 256>>>(e, n);
    k_scan   <<<1, 1024>>>(n);
    k_scatter<<<(e + n + 255) / 256, 256>>>(e, n);

    dim3 g01((n + 127) / 128, 2);              // N=256
    dim3 g2 ((n + 127) / 128, 1);              // N=64

    // ---- layer 0: x[N,128] @ W0 -> bufA; softmax/agg -> bufB (relu) ----
    k_gemm_tc<128, 64, 32><<<g01, 256>>>(x, W0, bufA, n, 256, 128);
    k_alpha<4><<<wblocks, 256>>>(bufA, a0s, a0d, n);
    k_att<4><<<wblocks, 256>>>(n);
    k_agg<4, true><<<n, 256>>>(bufA, b0, bufB, n);

    // ---- layer 1: bufB @ W1 -> bufA; -> bufB (relu) ----
    k_gemm_tc<128, 64, 32><<<g01, 256>>>(bufB, W1, bufA, n, 256, 256);
    k_alpha<4><<<wblocks, 256>>>(bufA, a1s, a1d, n);
    k_att<4><<<wblocks, 256>>>(n);
    k_agg<4, true><<<n, 256>>>(bufA, b1, bufB, n);

    // ---- layer 2: bufB @ W2 -> h2; -> out2 (no relu) ----
    k_gemm_tc<64, 32, 32><<<g2, 256>>>(bufB, W2, h2p, n, 64, 256);
    k_alpha<1><<<wblocks, 256>>>(h2p, a2s, a2d, n);
    k_att<1><<<wblocks, 256>>>(n);
    k_agg<1, false><<<n, 64>>>(h2p, b2, out2p, n);

    // ---- mean over nodes + linear head ----
    k_reduce<<<(n + 255) / 256, 256>>>(out2p, n);
    k_head<<<1, 64>>>(hw, hb, out, 1.0f / (float)n);
}